// round 8
// baseline (speedup 1.0000x reference)
#include <cuda_runtime.h>
#include <cooperative_groups.h>

namespace cg = cooperative_groups;

#define NG   512      // number of graphs
#define DIM  480      // feature dim
#define V    120      // float4 groups per row
#define NCH  224      // total channels (128 scalar + 64 l1 + 32 l2)
#define NSC  128      // scalar channels
#define EPSV 1e-5f
#define TPB  480      // 4 node-rows x 120 float4 lanes
#define ROWS 4

__device__ int g_off[NG + 1];   // g_off[g] = first node index with batch >= g

__device__ __forceinline__ int col_channel(int col) {
    if (col < 128) return col;                       // l=0
    if (col < 320) return 128 + (col - 128) / 3;     // l=1 (d=3)
    return 192 + (col - 320) / 5;                    // l=2 (d=5)
}

// Read batch id for node n under either dtype interpretation.
__device__ __forceinline__ int read_g(const void* __restrict__ b, int n, int is64) {
    if (is64) return (int)((const long long*)b)[n];
    return ((const int*)b)[n];
}

// batch sorted in [0, NG); N even. 32-bit word [N-1] is an odd index:
// int64 buffer -> high half == 0 ; int32 buffer -> batch[N-1] > 0 (w.p. ~1).
__device__ __forceinline__ int detect_is64(const void* __restrict__ b, int N) {
    return (((const int*)b)[N - 1] == 0) ? 1 : 0;
}

// ---------------------------------------------------------------------------
// Prep: boundary scan of sorted batch -> segment offsets g_off[0..NG].
// ---------------------------------------------------------------------------
__global__ void prep_kernel(const void* __restrict__ batch, int N) {
    const int is64 = detect_is64(batch, N);
    for (int n = blockIdx.x * blockDim.x + threadIdx.x; n < N;
         n += gridDim.x * blockDim.x) {
        int gn = read_g(batch, n, is64);
        if (n == 0) {
            for (int g = 0; g <= gn; g++) g_off[g] = 0;
        } else {
            int gp = read_g(batch, n - 1, is64);
            for (int g = gp + 1; g <= gn; g++) g_off[g] = n;
        }
        if (n == N - 1) {
            for (int g = gn + 1; g <= NG; g++) g_off[g] = N;
        }
    }
}

// ---------------------------------------------------------------------------
// Fused, clustered, occupancy-2: one GRAPH per 2-CTA cluster; each CTA
// handles half the graph's slab (~375KB). TPB=480 with launch_bounds(480,2)
// puts 2 CTAs on each SM, so one CTA's sync/params/tail bubbles overlap the
// other CTA's streaming (this is what held DRAM at 60% at occ=1).
// Phase A: local stats in smem -> ONE cluster.sync -> combine peer partials
// via DSMEM -> params (__syncthreads only) -> Phase B: re-read own half
// (L2-hot: resident window 304 x 375KB ~ 114MB < 126MB L2) + streaming write.
// Trailing cluster.sync preserves SMEM lifetime for peer DSMEM reads.
// ---------------------------------------------------------------------------
__global__ __launch_bounds__(TPB, 2) __cluster_dims__(2, 1, 1)
void fused_kernel(
    const float4* __restrict__ in4, float4* __restrict__ out4,
    const float* __restrict__ w, const float* __restrict__ bias)
{
    __shared__ float s_sq[DIM];             // per-column partial sum of squares
    __shared__ float s_sum[NSC];            // per-column partial sum (scalars)
    __shared__ float s_scale[NCH], s_beta[NCH];
    __shared__ int s_range[4];              // mylo, myhi, glo, ghi

    cg::cluster_group cluster = cg::this_cluster();
    const unsigned rank = cluster.block_rank();   // 0 or 1
    const int g    = blockIdx.x >> 1;
    const int tid  = threadIdx.x;
    const int lane = tid % V;
    const int row  = tid / V;
    const int col0 = lane * 4;
    const int c0 = col_channel(col0),     c1 = col_channel(col0 + 1);
    const int c2 = col_channel(col0 + 2), c3 = col_channel(col0 + 3);
    const bool sc = (col0 < NSC);

    if (tid == 0) {
        int glo = g_off[g], ghi = g_off[g + 1];
        int mid = (glo + ghi) >> 1;
        s_range[0] = rank ? mid : glo;
        s_range[1] = rank ? ghi : mid;
        s_range[2] = glo;
        s_range[3] = ghi;
    }
    for (int i = tid; i < DIM; i += TPB) s_sq[i] = 0.f;
    for (int i = tid; i < NSC; i += TPB) s_sum[i] = 0.f;
    __syncthreads();

    const int lo = s_range[0], hi = s_range[1];
    const float4* __restrict__ base = in4 + lane;

    // ---- Phase A: accumulate partial stats over my half (unrolled x2) ----
    float q0 = 0.f, q1 = 0.f, q2 = 0.f, q3 = 0.f;
    float s0 = 0.f, s1 = 0.f, s2 = 0.f, s3 = 0.f;
    int n = lo + row;
    for (; n + ROWS < hi; n += 2 * ROWS) {
        float4 xa = __ldg(base + (size_t)n * V);
        float4 xb = __ldg(base + (size_t)(n + ROWS) * V);
        q0 = fmaf(xa.x, xa.x, q0); q1 = fmaf(xa.y, xa.y, q1);
        q2 = fmaf(xa.z, xa.z, q2); q3 = fmaf(xa.w, xa.w, q3);
        q0 = fmaf(xb.x, xb.x, q0); q1 = fmaf(xb.y, xb.y, q1);
        q2 = fmaf(xb.z, xb.z, q2); q3 = fmaf(xb.w, xb.w, q3);
        if (sc) {
            s0 += xa.x + xb.x; s1 += xa.y + xb.y;
            s2 += xa.z + xb.z; s3 += xa.w + xb.w;
        }
    }
    if (n < hi) {
        float4 x = __ldg(base + (size_t)n * V);
        q0 = fmaf(x.x, x.x, q0); q1 = fmaf(x.y, x.y, q1);
        q2 = fmaf(x.z, x.z, q2); q3 = fmaf(x.w, x.w, q3);
        if (sc) { s0 += x.x; s1 += x.y; s2 += x.z; s3 += x.w; }
    }
    atomicAdd(&s_sq[col0 + 0], q0); atomicAdd(&s_sq[col0 + 1], q1);
    atomicAdd(&s_sq[col0 + 2], q2); atomicAdd(&s_sq[col0 + 3], q3);
    if (sc) {
        atomicAdd(&s_sum[col0 + 0], s0); atomicAdd(&s_sum[col0 + 1], s1);
        atomicAdd(&s_sum[col0 + 2], s2); atomicAdd(&s_sum[col0 + 3], s3);
    }

    // ---- Combine partials across the CTA pair (only mid-kernel barrier) ----
    cluster.sync();   // partial stats of both CTAs visible cluster-wide

    const float* peer_sq  = cluster.map_shared_rank(s_sq,  rank ^ 1);
    const float* peer_sum = cluster.map_shared_rank(s_sum, rank ^ 1);

    if (tid < NCH) {
        const int t = tid;
        const float cntf = fmaxf((float)(s_range[3] - s_range[2]), 1.0f);
        float scale, beta;
        if (t < NSC) {
            float mean = (s_sum[t] + peer_sum[t]) / cntf;
            float sq   = s_sq[t] + peer_sq[t];
            float var  = fmaxf(sq / cntf - mean * mean, 0.0f);
            scale = rsqrtf(var + EPSV) * w[t];
            beta  = bias[t] - mean * scale;
        } else if (t < 192) {
            int b0 = 128 + (t - 128) * 3;
            float sq = (s_sq[b0]     + peer_sq[b0])
                     + (s_sq[b0 + 1] + peer_sq[b0 + 1])
                     + (s_sq[b0 + 2] + peer_sq[b0 + 2]);
            scale = rsqrtf(sq / (3.0f * cntf) + EPSV) * w[t];
            beta  = 0.f;
        } else {
            int b0 = 320 + (t - 192) * 5;
            float sq = (s_sq[b0]     + peer_sq[b0])
                     + (s_sq[b0 + 1] + peer_sq[b0 + 1])
                     + (s_sq[b0 + 2] + peer_sq[b0 + 2])
                     + (s_sq[b0 + 3] + peer_sq[b0 + 3])
                     + (s_sq[b0 + 4] + peer_sq[b0 + 4]);
            scale = rsqrtf(sq / (5.0f * cntf) + EPSV) * w[t];
            beta  = 0.f;
        }
        s_scale[t] = scale;
        s_beta[t]  = beta;
    }

    // Params only need block-local visibility; s_sq is read-only from here.
    __syncthreads();

    // ---- Phase B: apply over my half (reads L2-hot; stream both paths) ----
    const float4 scv = make_float4(s_scale[c0], s_scale[c1], s_scale[c2], s_scale[c3]);
    const float4 btv = make_float4(s_beta[c0],  s_beta[c1],  s_beta[c2],  s_beta[c3]);
    float4* __restrict__ obase = out4 + lane;
    n = lo + row;
    for (; n + ROWS < hi; n += 2 * ROWS) {
        float4 xa = __ldcs(base + (size_t)n * V);
        float4 xb = __ldcs(base + (size_t)(n + ROWS) * V);
        float4 oa, ob;
        oa.x = fmaf(xa.x, scv.x, btv.x); oa.y = fmaf(xa.y, scv.y, btv.y);
        oa.z = fmaf(xa.z, scv.z, btv.z); oa.w = fmaf(xa.w, scv.w, btv.w);
        ob.x = fmaf(xb.x, scv.x, btv.x); ob.y = fmaf(xb.y, scv.y, btv.y);
        ob.z = fmaf(xb.z, scv.z, btv.z); ob.w = fmaf(xb.w, scv.w, btv.w);
        __stcs(obase + (size_t)n * V, oa);
        __stcs(obase + (size_t)(n + ROWS) * V, ob);
    }
    if (n < hi) {
        float4 x = __ldcs(base + (size_t)n * V);
        float4 o;
        o.x = fmaf(x.x, scv.x, btv.x); o.y = fmaf(x.y, scv.y, btv.y);
        o.z = fmaf(x.z, scv.z, btv.z); o.w = fmaf(x.w, scv.w, btv.w);
        __stcs(obase + (size_t)n * V, o);
    }

    // SMEM-lifetime safety: peer's DSMEM reads of my s_sq/s_sum must be done
    // before my SMEM is recycled. Both halves finish nearly together.
    cluster.sync();
}

// ---------------------------------------------------------------------------
extern "C" void kernel_launch(void* const* d_in, const int* in_sizes, int n_in,
                              void* d_out, int out_size)
{
    const float* inp   = (const float*)d_in[0];   // (N, 480) f32
    const float* w     = (const float*)d_in[1];   // (224,)   f32
    const float* bias  = (const float*)d_in[2];   // (128,)   f32
    const void*  batch = (const void*)d_in[3];    // (N,) int32 or int64, sorted
    float*       out   = (float*)d_out;

    const int N = in_sizes[0] / DIM;              // dtype-independent node count

    prep_kernel<<<304, 256>>>(batch, N);
    fused_kernel<<<NG * 2, TPB>>>((const float4*)inp, (float4*)out, w, bias);
}

// round 10
// speedup vs baseline: 1.1817x; 1.1817x over previous
#include <cuda_runtime.h>
#include <cooperative_groups.h>

namespace cg = cooperative_groups;

#define NG   512      // number of graphs
#define DIM  480      // feature dim
#define V    120      // float4 groups per row
#define NCH  224      // total channels (128 scalar + 64 l1 + 32 l2)
#define NSC  128      // scalar channels
#define EPSV 1e-5f
#define TPB  480      // 4 node-rows x 120 float4 lanes
#define ROWS 4
#define CSZ  4        // CTAs per cluster (one graph per cluster)

__device__ int g_off[NG + 1];   // g_off[g] = first node index with batch >= g

__device__ __forceinline__ int col_channel(int col) {
    if (col < 128) return col;                       // l=0
    if (col < 320) return 128 + (col - 128) / 3;     // l=1 (d=3)
    return 192 + (col - 320) / 5;                    // l=2 (d=5)
}

// Read batch id for node n under either dtype interpretation.
__device__ __forceinline__ int read_g(const void* __restrict__ b, int n, int is64) {
    if (is64) return (int)((const long long*)b)[n];
    return ((const int*)b)[n];
}

// batch sorted in [0, NG); N even. 32-bit word [N-1] is an odd index:
// int64 buffer -> high half == 0 ; int32 buffer -> batch[N-1] > 0 (w.p. ~1).
__device__ __forceinline__ int detect_is64(const void* __restrict__ b, int N) {
    return (((const int*)b)[N - 1] == 0) ? 1 : 0;
}

// ---------------------------------------------------------------------------
// Prep: boundary scan of sorted batch -> segment offsets g_off[0..NG].
// ---------------------------------------------------------------------------
__global__ void prep_kernel(const void* __restrict__ batch, int N) {
    const int is64 = detect_is64(batch, N);
    for (int n = blockIdx.x * blockDim.x + threadIdx.x; n < N;
         n += gridDim.x * blockDim.x) {
        int gn = read_g(batch, n, is64);
        if (n == 0) {
            for (int g = 0; g <= gn; g++) g_off[g] = 0;
        } else {
            int gp = read_g(batch, n - 1, is64);
            for (int g = gp + 1; g <= gn; g++) g_off[g] = n;
        }
        if (n == N - 1) {
            for (int g = gn + 1; g <= NG; g++) g_off[g] = N;
        }
    }
}

// ---------------------------------------------------------------------------
// Fused, 4-CTA clustered, occupancy-2: one GRAPH per cluster; each CTA
// handles a QUARTER slab (~187KB). occ=2 (TPB=480, launch_bounds(480,2))
// overlaps sync/params/tail bubbles across co-resident CTAs; the quarter
// slab keeps the live L2 footprint (input + write-allocated transients,
// ~270 CTAs x 187KB x ~2 ~ 100MB) under the 126MB L2 so phase-B re-reads
// stay L2-hot (R8 showed 304 x 375KB x 2 ~ 170MB thrashes).
// Phase A: local stats in smem -> ONE cluster.sync -> combine 4 ranks'
// partials via DSMEM -> params (__syncthreads) -> Phase B apply.
// ---------------------------------------------------------------------------
__global__ __launch_bounds__(TPB, 2) __cluster_dims__(CSZ, 1, 1)
void fused_kernel(
    const float4* __restrict__ in4, float4* __restrict__ out4,
    const float* __restrict__ w, const float* __restrict__ bias)
{
    __shared__ float s_sq[DIM];             // per-column partial sum of squares
    __shared__ float s_sum[NSC];            // per-column partial sum (scalars)
    __shared__ float s_scale[NCH], s_beta[NCH];
    __shared__ int s_range[4];              // mylo, myhi, glo, ghi

    cg::cluster_group cluster = cg::this_cluster();
    const unsigned rank = cluster.block_rank();   // 0..3
    const int g    = blockIdx.x / CSZ;
    const int tid  = threadIdx.x;
    const int lane = tid % V;
    const int row  = tid / V;
    const int col0 = lane * 4;
    const int c0 = col_channel(col0),     c1 = col_channel(col0 + 1);
    const int c2 = col_channel(col0 + 2), c3 = col_channel(col0 + 3);
    const bool sc = (col0 < NSC);

    if (tid == 0) {
        int glo = g_off[g], ghi = g_off[g + 1];
        int len = ghi - glo;
        s_range[0] = glo + (len * (int)rank) / CSZ;
        s_range[1] = glo + (len * ((int)rank + 1)) / CSZ;
        s_range[2] = glo;
        s_range[3] = ghi;
    }
    for (int i = tid; i < DIM; i += TPB) s_sq[i] = 0.f;
    for (int i = tid; i < NSC; i += TPB) s_sum[i] = 0.f;
    __syncthreads();

    const int lo = s_range[0], hi = s_range[1];
    const float4* __restrict__ base = in4 + lane;

    // ---- Phase A: accumulate partial stats over my quarter (unroll x2) ----
    float q0 = 0.f, q1 = 0.f, q2 = 0.f, q3 = 0.f;
    float s0 = 0.f, s1 = 0.f, s2 = 0.f, s3 = 0.f;
    int n = lo + row;
    for (; n + ROWS < hi; n += 2 * ROWS) {
        float4 xa = __ldg(base + (size_t)n * V);
        float4 xb = __ldg(base + (size_t)(n + ROWS) * V);
        q0 = fmaf(xa.x, xa.x, q0); q1 = fmaf(xa.y, xa.y, q1);
        q2 = fmaf(xa.z, xa.z, q2); q3 = fmaf(xa.w, xa.w, q3);
        q0 = fmaf(xb.x, xb.x, q0); q1 = fmaf(xb.y, xb.y, q1);
        q2 = fmaf(xb.z, xb.z, q2); q3 = fmaf(xb.w, xb.w, q3);
        if (sc) {
            s0 += xa.x + xb.x; s1 += xa.y + xb.y;
            s2 += xa.z + xb.z; s3 += xa.w + xb.w;
        }
    }
    if (n < hi) {
        float4 x = __ldg(base + (size_t)n * V);
        q0 = fmaf(x.x, x.x, q0); q1 = fmaf(x.y, x.y, q1);
        q2 = fmaf(x.z, x.z, q2); q3 = fmaf(x.w, x.w, q3);
        if (sc) { s0 += x.x; s1 += x.y; s2 += x.z; s3 += x.w; }
    }
    atomicAdd(&s_sq[col0 + 0], q0); atomicAdd(&s_sq[col0 + 1], q1);
    atomicAdd(&s_sq[col0 + 2], q2); atomicAdd(&s_sq[col0 + 3], q3);
    if (sc) {
        atomicAdd(&s_sum[col0 + 0], s0); atomicAdd(&s_sum[col0 + 1], s1);
        atomicAdd(&s_sum[col0 + 2], s2); atomicAdd(&s_sum[col0 + 3], s3);
    }

    // ---- Combine partials across the 4-CTA cluster ----
    cluster.sync();   // all ranks' partial stats visible cluster-wide

    const float* p_sq [CSZ];
    const float* p_sum[CSZ];
    #pragma unroll
    for (int r = 0; r < CSZ; r++) {
        p_sq[r]  = cluster.map_shared_rank(s_sq,  r);
        p_sum[r] = cluster.map_shared_rank(s_sum, r);
    }

    if (tid < NCH) {
        const int t = tid;
        const float cntf = fmaxf((float)(s_range[3] - s_range[2]), 1.0f);
        float scale, beta;
        if (t < NSC) {
            float sm = 0.f, sq = 0.f;
            #pragma unroll
            for (int r = 0; r < CSZ; r++) { sm += p_sum[r][t]; sq += p_sq[r][t]; }
            float mean = sm / cntf;
            float var  = fmaxf(sq / cntf - mean * mean, 0.0f);
            scale = rsqrtf(var + EPSV) * w[t];
            beta  = bias[t] - mean * scale;
        } else if (t < 192) {
            int b0 = 128 + (t - 128) * 3;
            float sq = 0.f;
            #pragma unroll
            for (int r = 0; r < CSZ; r++)
                sq += p_sq[r][b0] + p_sq[r][b0 + 1] + p_sq[r][b0 + 2];
            scale = rsqrtf(sq / (3.0f * cntf) + EPSV) * w[t];
            beta  = 0.f;
        } else {
            int b0 = 320 + (t - 192) * 5;
            float sq = 0.f;
            #pragma unroll
            for (int r = 0; r < CSZ; r++)
                sq += p_sq[r][b0] + p_sq[r][b0 + 1] + p_sq[r][b0 + 2]
                    + p_sq[r][b0 + 3] + p_sq[r][b0 + 4];
            scale = rsqrtf(sq / (5.0f * cntf) + EPSV) * w[t];
            beta  = 0.f;
        }
        s_scale[t] = scale;
        s_beta[t]  = beta;
    }

    // Params only need block-local visibility; s_sq is read-only from here.
    __syncthreads();

    // ---- Phase B: apply over my quarter (reads L2-hot; stream both) ----
    const float4 scv = make_float4(s_scale[c0], s_scale[c1], s_scale[c2], s_scale[c3]);
    const float4 btv = make_float4(s_beta[c0],  s_beta[c1],  s_beta[c2],  s_beta[c3]);
    float4* __restrict__ obase = out4 + lane;
    n = lo + row;
    for (; n + ROWS < hi; n += 2 * ROWS) {
        float4 xa = __ldcs(base + (size_t)n * V);
        float4 xb = __ldcs(base + (size_t)(n + ROWS) * V);
        float4 oa, ob;
        oa.x = fmaf(xa.x, scv.x, btv.x); oa.y = fmaf(xa.y, scv.y, btv.y);
        oa.z = fmaf(xa.z, scv.z, btv.z); oa.w = fmaf(xa.w, scv.w, btv.w);
        ob.x = fmaf(xb.x, scv.x, btv.x); ob.y = fmaf(xb.y, scv.y, btv.y);
        ob.z = fmaf(xb.z, scv.z, btv.z); ob.w = fmaf(xb.w, scv.w, btv.w);
        __stcs(obase + (size_t)n * V, oa);
        __stcs(obase + (size_t)(n + ROWS) * V, ob);
    }
    if (n < hi) {
        float4 x = __ldcs(base + (size_t)n * V);
        float4 o;
        o.x = fmaf(x.x, scv.x, btv.x); o.y = fmaf(x.y, scv.y, btv.y);
        o.z = fmaf(x.z, scv.z, btv.z); o.w = fmaf(x.w, scv.w, btv.w);
        __stcs(obase + (size_t)n * V, o);
    }

    // SMEM-lifetime safety: peers' DSMEM reads of my partials must complete
    // before my SMEM is recycled. All quarters finish nearly together.
    cluster.sync();
}

// ---------------------------------------------------------------------------
extern "C" void kernel_launch(void* const* d_in, const int* in_sizes, int n_in,
                              void* d_out, int out_size)
{
    const float* inp   = (const float*)d_in[0];   // (N, 480) f32
    const float* w     = (const float*)d_in[1];   // (224,)   f32
    const float* bias  = (const float*)d_in[2];   // (128,)   f32
    const void*  batch = (const void*)d_in[3];    // (N,) int32 or int64, sorted
    float*       out   = (float*)d_out;

    const int N = in_sizes[0] / DIM;              // dtype-independent node count

    prep_kernel<<<304, 256>>>(batch, N);
    fused_kernel<<<NG * CSZ, TPB>>>((const float4*)inp, (float4*)out, w, bias);
}